// round 11
// baseline (speedup 1.0000x reference)
#include <cuda_runtime.h>
#include <cstdint>

#define KST   48
#define TLEN  512
#define TILE  8               // steps per tile (= renorm cadence)
#define BDIM  64              // 2 warps; 1 batch per warp
#define ETS   416             // per-warp tile float stride

// ---- packed f32x2 helpers (sm_100+) ----
__device__ __forceinline__ unsigned long long fma2(unsigned long long a,
                                                   unsigned long long b,
                                                   unsigned long long c) {
    unsigned long long d;
    asm("fma.rn.f32x2 %0, %1, %2, %3;" : "=l"(d) : "l"(a), "l"(b), "l"(c));
    return d;
}
__device__ __forceinline__ unsigned long long add2(unsigned long long a,
                                                   unsigned long long b) {
    unsigned long long d;
    asm("add.rn.f32x2 %0, %1, %2;" : "=l"(d) : "l"(a), "l"(b));
    return d;
}
__device__ __forceinline__ unsigned long long pack2(float lo, float hi) {
    unsigned long long r;
    asm("mov.b64 %0, {%1, %2};" : "=l"(r) : "f"(lo), "f"(hi));
    return r;
}
__device__ __forceinline__ float2 unpack2(unsigned long long v) {
    float2 f;
    asm("mov.b64 {%0, %1}, %2;" : "=f"(f.x), "=f"(f.y) : "l"(v));
    return f;
}
__device__ __forceinline__ float ex2f(float x) {
    float y; asm("ex2.approx.f32 %0, %1;" : "=f"(y) : "f"(x)); return y;
}
__device__ __forceinline__ float lg2f(float x) {
    float y; asm("lg2.approx.f32 %0, %1;" : "=f"(y) : "f"(x)); return y;
}

#define LOG2E 1.4426950408889634f
#define LN2   0.6931471805599453f

__global__ __launch_bounds__(BDIM)
void crf_nll_kernel(const float* __restrict__ emis,   // [B, T, K]
                    const int*   __restrict__ lab,    // [B, T]
                    const float* __restrict__ trans,  // [K, K]
                    float*       __restrict__ out)    // [B]
{
    __shared__ __align__(16) float etile[2][ETS];        // per-warp EXP'd emission tile
    __shared__ __align__(16) float pbuf[2][2][KST];      // [parity][warp][state]

    const int tid = threadIdx.x;
    const int w   = tid >> 5;          // warp in block = batch
    const int l   = tid & 31;          // lane
    const int b   = blockIdx.x * 2 + w;
    // lane owns cols l and j2; pad lanes (l>=16) duplicate col 0 (result masked at end)
    const int j2  = (l < 16) ? (l + 32) : 0;

    const float* eb = emis + (size_t)b * TLEN * KST;
    const int*   lb = lab  + b * TLEN;

    // E columns (exp'd) as 24 packed f32x2 each (pairs over source state i)
    unsigned long long ecA[KST / 2], ecB[KST / 2];
#pragma unroll
    for (int q = 0; q < KST / 2; ++q) {
        const float* t0 = trans + (2 * q) * KST;
        const float* t1 = trans + (2 * q + 1) * KST;
        ecA[q] = pack2(__expf(t0[l]),  __expf(t1[l]));
        ecB[q] = pack2(__expf(t0[j2]), __expf(t1[j2]));
    }

    // ---- sequence score (unary + binary), strided over 32 lanes ----
    float part = 0.f;
    for (int t = l; t < TLEN; t += 32) {
        int l0 = lb[t];
        part += eb[t * KST + l0];
        if (t + 1 < TLEN) part += trans[l0 * KST + lb[t + 1]];
    }
#pragma unroll
    for (int d = 16; d >= 1; d >>= 1)
        part += __shfl_xor_sync(0xffffffffu, part, d);
    const float score = part;

    // ---- forward recursion, LINEAR domain with exact pow2 renorm ----
    float p0 = ex2f(eb[l]  * LOG2E);
    float p1 = ex2f(eb[j2] * LOG2E);
    float M  = 0.f;                      // accumulated log2 scale (integer-valued)

    const float4* src4  = (const float4*)eb;
    const int     maxf4 = (TLEN * KST) / 4 - 1;    // 6143
    float*        myTile = &etile[w][0];
    float*        pb0 = &pbuf[0][w][0];
    float*        pb1 = &pbuf[1][w][0];

    // prefetch tile 0 (t = 1..8): 96 float4, 3 per lane
    float4 r0 = src4[12 + l], r1 = src4[44 + l], r2 = src4[76 + l];

    int par = 0;
    for (int gt = 0; gt < 64; ++gt) {
        // renormalize: exact power-of-2 scale (pad lanes hold duplicated real values)
        float m = fmaxf(p0, p1);
#pragma unroll
        for (int d = 16; d >= 1; d >>= 1)
            m = fmaxf(m, __shfl_xor_sync(0xffffffffu, m, d));
        float kk = ceilf(lg2f(m));
        float sc = ex2f(-kk);            // exact pow2: error-free rescale
        p0 *= sc; p1 *= sc;
        M  += kk;

        // commit current tile as EXP'd weights: w = exp(e)
        {
            float4 v;
            v = r0;
            v.x = ex2f(v.x * LOG2E); v.y = ex2f(v.y * LOG2E);
            v.z = ex2f(v.z * LOG2E); v.w = ex2f(v.w * LOG2E);
            ((float4*)myTile)[l] = v;
            v = r1;
            v.x = ex2f(v.x * LOG2E); v.y = ex2f(v.y * LOG2E);
            v.z = ex2f(v.z * LOG2E); v.w = ex2f(v.w * LOG2E);
            ((float4*)myTile)[32 + l] = v;
            v = r2;
            v.x = ex2f(v.x * LOG2E); v.y = ex2f(v.y * LOG2E);
            v.z = ex2f(v.z * LOG2E); v.w = ex2f(v.w * LOG2E);
            ((float4*)myTile)[64 + l] = v;
        }

        // prefetch next tile (clamped rows only land in unread tail pad)
        if (gt + 1 < 64) {
            int base = (9 + TILE * gt) * (KST / 4);
            r0 = src4[min(base + l,      maxf4)];
            r1 = src4[min(base + 32 + l, maxf4)];
            r2 = src4[min(base + 64 + l, maxf4)];
        }
        __syncwarp();

#pragma unroll
        for (int tt = 0; tt < TILE; ++tt) {
            const int t = 1 + TILE * gt + tt;
            if (t >= TLEN) break;                 // uniform

            float* pb = par ? pb1 : pb0;
            pb[l] = p0;
            if (l < 16) pb[l + 32] = p1;
            __syncwarp();

            // pre-exponentiated weights: plain LDS, no MUFU on the chain
            float w0 = myTile[tt * KST + l];
            float w1 = myTile[tt * KST + j2];

            // 2 outputs x 4 chains of depth 6; 48 fma2 per lane
            const ulonglong2* pp = (const ulonglong2*)pb;
            unsigned long long cA[4] = {0,0,0,0}, cB[4] = {0,0,0,0};
#pragma unroll
            for (int q = 0; q < KST / 4; ++q) {   // 12 x LDS.128 broadcast
                ulonglong2 v = pp[q];
                const int h0 = (2 * q)     & 3;
                const int h1 = (2 * q + 1) & 3;
                cA[h0] = fma2(v.x, ecA[2 * q],     cA[h0]);
                cA[h1] = fma2(v.y, ecA[2 * q + 1], cA[h1]);
                cB[h0] = fma2(v.x, ecB[2 * q],     cB[h0]);
                cB[h1] = fma2(v.y, ecB[2 * q + 1], cB[h1]);
            }
            float2 f0 = unpack2(add2(add2(cA[0], cA[1]), add2(cA[2], cA[3])));
            float2 f1 = unpack2(add2(add2(cB[0], cB[1]), add2(cB[2], cB[3])));

            p0 = (f0.x + f0.y) * w0;              // no log/exp on the chain
            p1 = (f1.x + f1.y) * w1;
            par ^= 1;
        }
    }

    // ---- final: log_norm = ln(sum p) + ln2 * M; mask duplicated pad columns ----
    float ssum = p0 + ((l < 16) ? p1 : 0.f);
#pragma unroll
    for (int d = 16; d >= 1; d >>= 1)
        ssum += __shfl_xor_sync(0xffffffffu, ssum, d);

    if (l == 0)
        out[b] = LN2 * (lg2f(ssum) + M) - score;
}

extern "C" void kernel_launch(void* const* d_in, const int* in_sizes, int n_in,
                              void* d_out, int out_size)
{
    const float* emis  = (const float*)d_in[0];   // output (B,T,K) fp32
    const int*   lab   = (const int*)  d_in[1];   // label_input (B,T) int32
    const float* trans = (const float*)d_in[2];   // transition_params (K,K) fp32
    float*       outp  = (float*)d_out;           // (B,) fp32

    const int B = out_size;                       // 1024
    crf_nll_kernel<<<B / 2, BDIM>>>(emis, lab, trans, outp);
}

// round 12
// speedup vs baseline: 1.1215x; 1.1215x over previous
#include <cuda_runtime.h>
#include <cstdint>

#define KST   48
#define TLEN  512
#define GRP   16              // lanes per batch
#define NB    2               // batches per block (one warp)
#define BDIM  32
#define TILE  8               // steps per tile (= renorm cadence)
#define ETS   400             // etile per-batch float stride (bank offset 16)

// ---- packed f32x2 helpers (sm_100+) ----
__device__ __forceinline__ unsigned long long fma2(unsigned long long a,
                                                   unsigned long long b,
                                                   unsigned long long c) {
    unsigned long long d;
    asm("fma.rn.f32x2 %0, %1, %2, %3;" : "=l"(d) : "l"(a), "l"(b), "l"(c));
    return d;
}
__device__ __forceinline__ unsigned long long add2(unsigned long long a,
                                                   unsigned long long b) {
    unsigned long long d;
    asm("add.rn.f32x2 %0, %1, %2;" : "=l"(d) : "l"(a), "l"(b));
    return d;
}
__device__ __forceinline__ unsigned long long pack2(float lo, float hi) {
    unsigned long long r;
    asm("mov.b64 %0, {%1, %2};" : "=l"(r) : "f"(lo), "f"(hi));
    return r;
}
__device__ __forceinline__ float2 unpack2(unsigned long long v) {
    float2 f;
    asm("mov.b64 {%0, %1}, %2;" : "=f"(f.x), "=f"(f.y) : "l"(v));
    return f;
}
__device__ __forceinline__ float ex2f(float x) {
    float y; asm("ex2.approx.f32 %0, %1;" : "=f"(y) : "f"(x)); return y;
}
__device__ __forceinline__ float lg2f(float x) {
    float y; asm("lg2.approx.f32 %0, %1;" : "=f"(y) : "f"(x)); return y;
}
// zero-instruction ordering fence: warp is branch-convergent in the step loop,
// so same-warp LSU program order makes STS->LDS safe; this only stops the
// compiler from reordering across it.
__device__ __forceinline__ void cfence() { asm volatile("" ::: "memory"); }

#define LOG2E 1.4426950408889634f
#define LN2   0.6931471805599453f

// one recursion step (no per-step syncwarp, no bounds check)
#define STEP(TT)                                                               \
{                                                                              \
    float* pb = ((TT) & 1) ? pb1 : pb0;                                        \
    pb[l] = p0; pb[l + 16] = p1; pb[l + 32] = p2;                              \
    cfence();                                                                  \
    float w0 = myTile[(TT) * KST + l];                                         \
    float w1 = myTile[(TT) * KST + l + 16];                                    \
    float w2 = myTile[(TT) * KST + l + 32];                                    \
    const ulonglong2* pp = (const ulonglong2*)pb;                              \
    unsigned long long cA[4] = {0,0,0,0}, cB[4] = {0,0,0,0}, cC[4] = {0,0,0,0};\
    _Pragma("unroll")                                                          \
    for (int q = 0; q < KST / 4; ++q) {                                        \
        ulonglong2 v = pp[q];                                                  \
        const int h0 = (2 * q)     & 3;                                        \
        const int h1 = (2 * q + 1) & 3;                                        \
        cA[h0] = fma2(v.x, ecA[2 * q],     cA[h0]);                            \
        cA[h1] = fma2(v.y, ecA[2 * q + 1], cA[h1]);                            \
        cB[h0] = fma2(v.x, ecB[2 * q],     cB[h0]);                            \
        cB[h1] = fma2(v.y, ecB[2 * q + 1], cB[h1]);                            \
        cC[h0] = fma2(v.x, ecC[2 * q],     cC[h0]);                            \
        cC[h1] = fma2(v.y, ecC[2 * q + 1], cC[h1]);                            \
    }                                                                          \
    float2 f0 = unpack2(add2(add2(cA[0], cA[1]), add2(cA[2], cA[3])));         \
    float2 f1 = unpack2(add2(add2(cB[0], cB[1]), add2(cB[2], cB[3])));         \
    float2 f2 = unpack2(add2(add2(cC[0], cC[1]), add2(cC[2], cC[3])));         \
    p0 = (f0.x + f0.y) * w0;                                                   \
    p1 = (f1.x + f1.y) * w1;                                                   \
    p2 = (f2.x + f2.y) * w2;                                                   \
    cfence();                                                                  \
}

__global__ __launch_bounds__(BDIM)
void crf_nll_kernel(const float* __restrict__ emis,   // [B, T, K]
                    const int*   __restrict__ lab,    // [B, T]
                    const float* __restrict__ trans,  // [K, K]
                    float*       __restrict__ out)    // [B]
{
    __shared__ __align__(16) float etile[NB * ETS];      // EXP'd emission weights
    __shared__ __align__(16) float pbuf[2][NB][KST];     // ping-pong p (linear)

    const int tid = threadIdx.x;
    const int g   = tid >> 4;          // batch within block (0/1)
    const int l   = tid & 15;          // lane within batch group
    const int b   = blockIdx.x * NB + g;

    const float* eb = emis + (size_t)b * TLEN * KST;
    const int*   lb = lab  + b * TLEN;

    // E columns for states l, l+16, l+32 as 24 packed f32x2 each (pairs over i)
    unsigned long long ecA[KST / 2], ecB[KST / 2], ecC[KST / 2];
#pragma unroll
    for (int q = 0; q < KST / 2; ++q) {
        const float* t0 = trans + (2 * q) * KST;
        const float* t1 = trans + (2 * q + 1) * KST;
        ecA[q] = pack2(__expf(t0[l]),      __expf(t1[l]));
        ecB[q] = pack2(__expf(t0[l + 16]), __expf(t1[l + 16]));
        ecC[q] = pack2(__expf(t0[l + 32]), __expf(t1[l + 32]));
    }

    // ---- sequence score (unary + binary), strided over 16 lanes ----
    float part = 0.f;
    for (int t = l; t < TLEN; t += GRP) {
        int l0 = lb[t];
        part += eb[t * KST + l0];
        if (t + 1 < TLEN) part += trans[l0 * KST + lb[t + 1]];
    }
#pragma unroll
    for (int d = 8; d >= 1; d >>= 1)
        part += __shfl_xor_sync(0xffffffffu, part, d, 16);
    const float score = part;

    // ---- forward recursion, LINEAR domain with exact pow2 renorm ----
    float p0 = ex2f(eb[l]      * LOG2E);
    float p1 = ex2f(eb[l + 16] * LOG2E);
    float p2 = ex2f(eb[l + 32] * LOG2E);
    float M  = 0.f;                      // accumulated log2 scale (integer-valued)

    const float4* src4  = (const float4*)eb;
    const int     maxf4 = (TLEN * KST) / 4 - 1;
    float*        myTile = etile + g * ETS;
    float*        pb0 = &pbuf[0][g][0];
    float*        pb1 = &pbuf[1][g][0];

    // prefetch tile 0 (t = 1..8): 96 float4 per batch, 6 per lane
    float4 r[6];
#pragma unroll
    for (int k = 0; k < 6; ++k)
        r[k] = src4[12 + l + 16 * k];

    for (int gt = 0; gt < 63; ++gt) {            // 63 full tiles, no step checks
        // renormalize: exact power-of-2 scale so p stays in range
        float m = fmaxf(p0, fmaxf(p1, p2));
#pragma unroll
        for (int d = 8; d >= 1; d >>= 1)
            m = fmaxf(m, __shfl_xor_sync(0xffffffffu, m, d, 16));
        float kk = ceilf(lg2f(m));
        float sc = ex2f(-kk);            // exact pow2: error-free rescale
        p0 *= sc; p1 *= sc; p2 *= sc;
        M  += kk;

        // commit current tile as EXP'd weights: w = exp(e)
#pragma unroll
        for (int k = 0; k < 6; ++k) {
            float4 v = r[k];
            v.x = ex2f(v.x * LOG2E);
            v.y = ex2f(v.y * LOG2E);
            v.z = ex2f(v.z * LOG2E);
            v.w = ex2f(v.w * LOG2E);
            ((float4*)myTile)[l + 16 * k] = v;
        }

        // prefetch next tile (clamp only affects the never-consumed tail pad)
        {
            int base = (9 + TILE * gt) * (KST / 4);
#pragma unroll
            for (int k = 0; k < 6; ++k)
                r[k] = src4[min(base + l + 16 * k, maxf4)];
        }
        __syncwarp();                             // per-tile barrier (amortized)

        STEP(0) STEP(1) STEP(2) STEP(3)
        STEP(4) STEP(5) STEP(6) STEP(7)
    }

    // ---- tail tile: t = 505..511 (7 steps) ----
    {
        float m = fmaxf(p0, fmaxf(p1, p2));
#pragma unroll
        for (int d = 8; d >= 1; d >>= 1)
            m = fmaxf(m, __shfl_xor_sync(0xffffffffu, m, d, 16));
        float kk = ceilf(lg2f(m));
        float sc = ex2f(-kk);
        p0 *= sc; p1 *= sc; p2 *= sc;
        M  += kk;

#pragma unroll
        for (int k = 0; k < 6; ++k) {
            float4 v = r[k];
            v.x = ex2f(v.x * LOG2E);
            v.y = ex2f(v.y * LOG2E);
            v.z = ex2f(v.z * LOG2E);
            v.w = ex2f(v.w * LOG2E);
            ((float4*)myTile)[l + 16 * k] = v;
        }
        __syncwarp();

        STEP(0) STEP(1) STEP(2) STEP(3)
        STEP(4) STEP(5) STEP(6)
    }

    // ---- final: log_norm = ln(sum p) + ln2 * M ----
    float ssum = p0 + p1 + p2;
#pragma unroll
    for (int d = 8; d >= 1; d >>= 1)
        ssum += __shfl_xor_sync(0xffffffffu, ssum, d, 16);

    if (l == 0)
        out[b] = LN2 * (lg2f(ssum) + M) - score;
}

extern "C" void kernel_launch(void* const* d_in, const int* in_sizes, int n_in,
                              void* d_out, int out_size)
{
    const float* emis  = (const float*)d_in[0];   // output (B,T,K) fp32
    const int*   lab   = (const int*)  d_in[1];   // label_input (B,T) int32
    const float* trans = (const float*)d_in[2];   // transition_params (K,K) fp32
    float*       outp  = (float*)d_out;           // (B,) fp32

    const int B = out_size;                       // 1024
    crf_nll_kernel<<<B / NB, BDIM>>>(emis, lab, trans, outp);
}